// round 1
// baseline (speedup 1.0000x reference)
#include <cuda_runtime.h>
#include <cuda_bf16.h>
#include <math.h>

// Problem constants
#define BATCH 8
#define SEQ   1024
#define DMODEL 1024
#define HEADS 16
#define HDIM  64
#define MTOT  (BATCH * SEQ)     // 8192 rows

// -------------------- scratch (allocation-free rule: __device__ globals) ----
__device__ float g_q[(size_t)BATCH * HEADS * SEQ * HDIM];   // [B,H,S,Hd]
__device__ float g_k[(size_t)BATCH * HEADS * SEQ * HDIM];
__device__ float g_v[(size_t)BATCH * HEADS * SEQ * HDIM];
__device__ float g_ctx[(size_t)BATCH * SEQ * DMODEL];       // [B,S,D]

// -------------------- GEMM: C = A(MxK) * W(NxK)^T + bias ---------------------
#define GBM 128
#define GBN 128
#define GBK 16

__global__ __launch_bounds__(256)
void gemm_bias_kernel(const float* __restrict__ A, const float* __restrict__ W,
                      const float* __restrict__ bias, float* __restrict__ C,
                      int M, int N, int K, int split_heads)
{
    __shared__ float As[GBK][GBM];
    __shared__ float Bs[GBK][GBN];

    const int tid = threadIdx.x;
    const int m0 = blockIdx.y * GBM;
    const int n0 = blockIdx.x * GBN;
    const int ty = tid >> 4;      // 0..15
    const int tx = tid & 15;      // 0..15

    float acc[8][8];
#pragma unroll
    for (int i = 0; i < 8; i++)
#pragma unroll
        for (int j = 0; j < 8; j++) acc[i][j] = 0.0f;

    for (int kt = 0; kt < K; kt += GBK) {
        // Load A tile (128x16) and W tile (128x16) as float4, store transposed.
#pragma unroll
        for (int it = 0; it < 2; it++) {
            int idx = tid + it * 256;            // 0..511
            int r   = idx >> 2;                  // 0..127
            int vc  = (idx & 3) << 2;            // 0,4,8,12
            float4 a4 = *(const float4*)(A + (size_t)(m0 + r) * K + kt + vc);
            As[vc + 0][r] = a4.x; As[vc + 1][r] = a4.y;
            As[vc + 2][r] = a4.z; As[vc + 3][r] = a4.w;
            float4 w4 = *(const float4*)(W + (size_t)(n0 + r) * K + kt + vc);
            Bs[vc + 0][r] = w4.x; Bs[vc + 1][r] = w4.y;
            Bs[vc + 2][r] = w4.z; Bs[vc + 3][r] = w4.w;
        }
        __syncthreads();

#pragma unroll
        for (int kk = 0; kk < GBK; kk++) {
            float a[8], b[8];
            *(float4*)&a[0] = *(const float4*)&As[kk][ty * 8];
            *(float4*)&a[4] = *(const float4*)&As[kk][ty * 8 + 4];
            *(float4*)&b[0] = *(const float4*)&Bs[kk][tx * 8];
            *(float4*)&b[4] = *(const float4*)&Bs[kk][tx * 8 + 4];
#pragma unroll
            for (int i = 0; i < 8; i++)
#pragma unroll
                for (int j = 0; j < 8; j++)
                    acc[i][j] = fmaf(a[i], b[j], acc[i][j]);
        }
        __syncthreads();
    }

    // Epilogue
#pragma unroll
    for (int i = 0; i < 8; i++) {
        int m = m0 + ty * 8 + i;
        int bb = m >> 10;         // m / 1024
        int s  = m & 1023;
#pragma unroll
        for (int j = 0; j < 8; j++) {
            int n = n0 + tx * 8 + j;
            float val = acc[i][j] + bias[n];
            size_t idx;
            if (split_heads) {
                int h = n >> 6;   // head
                int d = n & 63;
                idx = ((((size_t)bb * HEADS + h) * SEQ + s) << 6) + d;
            } else {
                idx = (size_t)m * N + n;
            }
            C[idx] = val;
        }
    }
}

// -------------------- fused attention: scores -> softmax -> attn out -> ctx --
// One block handles (b,h) and 32 query rows. 256 threads.
#define QB 32
#define KT 128                  // keys per tile
#define QS_STRIDE 65
#define KS_STRIDE 140           // transposed k tile: ks_t[kk(0..63)][key(0..127)], %4==0, conflict-free by mapping
#define VS_STRIDE 68

// dynamic smem layout (floats):
//   sc   : QB * SEQ            = 32768
//   qs   : QB * QS_STRIDE      = 2080
//   ksvs : max(64*KS_STRIDE, KT*VS_STRIDE) = max(8960, 8704) = 8960
#define SC_FLOATS   (QB * SEQ)
#define QS_FLOATS   (QB * QS_STRIDE)
#define KSVS_FLOATS (64 * KS_STRIDE)
#define ATTN_SMEM_BYTES ((SC_FLOATS + QS_FLOATS + KSVS_FLOATS) * 4)

__global__ __launch_bounds__(256)
void attn_kernel(const float* __restrict__ q, const float* __restrict__ k,
                 const float* __restrict__ v, float* __restrict__ attn_out,
                 float* __restrict__ ctx_out)
{
    extern __shared__ float smem[];
    float* sc = smem;                        // [QB][SEQ]
    float* qs = sc + SC_FLOATS;              // [QB][QS_STRIDE]
    float* ksvs = qs + QS_FLOATS;            // k tile (transposed) or v tile

    const int tid = threadIdx.x;
    const int bh = blockIdx.x;               // 0..127  (b*16+h)
    const int qb = blockIdx.y;               // 0..31
    const int b = bh >> 4;
    const int h = bh & 15;

    const float* qbase = q + ((size_t)bh * SEQ + qb * QB) * HDIM;
    const float* kbase = k + (size_t)bh * SEQ * HDIM;
    const float* vbase = v + (size_t)bh * SEQ * HDIM;

    // ---- load Q rows (32x64) ----
    for (int i = tid; i < QB * HDIM; i += 256) {
        int r = i >> 6, c = i & 63;
        qs[r * QS_STRIDE + c] = qbase[i];
    }

    // ---- score phase ----
    const int qi = tid >> 3;                 // 0..31
    const int jg = tid & 7;                  // 0..7

    for (int kt = 0; kt < SEQ; kt += KT) {
        __syncthreads();
        // load K tile transposed: ks_t[c][key] with key in 0..127
        for (int i = tid; i < KT * HDIM; i += 256) {
            int key = i >> 6, c = i & 63;
            ksvs[c * KS_STRIDE + key] = kbase[(size_t)(kt + key) * HDIM + i % 64];
        }
        __syncthreads();

        float acc[16];
#pragma unroll
        for (int t = 0; t < 16; t++) acc[t] = 0.0f;

        for (int kk = 0; kk < HDIM; kk++) {
            float qv = qs[qi * QS_STRIDE + kk];
            const float* krow = &ksvs[kk * KS_STRIDE];
#pragma unroll
            for (int jj4 = 0; jj4 < 4; jj4++) {
                float4 kv = *(const float4*)&krow[jj4 * 32 + jg * 4];
                acc[jj4 * 4 + 0] = fmaf(qv, kv.x, acc[jj4 * 4 + 0]);
                acc[jj4 * 4 + 1] = fmaf(qv, kv.y, acc[jj4 * 4 + 1]);
                acc[jj4 * 4 + 2] = fmaf(qv, kv.z, acc[jj4 * 4 + 2]);
                acc[jj4 * 4 + 3] = fmaf(qv, kv.w, acc[jj4 * 4 + 3]);
            }
        }
        // write scaled scores to sc
#pragma unroll
        for (int jj4 = 0; jj4 < 4; jj4++)
#pragma unroll
            for (int c = 0; c < 4; c++) {
                int kj = jj4 * 32 + jg * 4 + c;
                sc[qi * SEQ + kt + kj] = acc[jj4 * 4 + c] * 0.125f;
            }
    }
    __syncthreads();

    // ---- softmax per row + write attn to global ----
    {
        const int wid = tid >> 5;
        const int lane = tid & 31;
        for (int r = wid * 4; r < wid * 4 + 4; r++) {
            float* row = &sc[r * SEQ];
            float mx = -1e30f;
            for (int c = lane; c < SEQ; c += 32) mx = fmaxf(mx, row[c]);
#pragma unroll
            for (int off = 16; off > 0; off >>= 1)
                mx = fmaxf(mx, __shfl_xor_sync(0xffffffffu, mx, off));
            float sum = 0.0f;
            for (int c = lane; c < SEQ; c += 32) {
                float e = __expf(row[c] - mx);
                row[c] = e;
                sum += e;
            }
#pragma unroll
            for (int off = 16; off > 0; off >>= 1)
                sum += __shfl_xor_sync(0xffffffffu, sum, off);
            float inv = 1.0f / sum;
            float* arow = attn_out + ((size_t)bh * SEQ + qb * QB + r) * SEQ;
            for (int c = lane; c < SEQ; c += 32) {
                float p = row[c] * inv;
                row[c] = p;
                arow[c] = p;
            }
        }
    }

    // ---- ctx phase: ctx[qi][d] = sum_k P[qi][k] * V[k][d] ----
    const int dg = tid & 7;                  // d = dg + 8*j
    float cacc[8];
#pragma unroll
    for (int j = 0; j < 8; j++) cacc[j] = 0.0f;

    for (int kt = 0; kt < SEQ; kt += KT) {
        __syncthreads();
        for (int i = tid; i < KT * HDIM; i += 256) {
            int key = i >> 6, c = i & 63;
            ksvs[key * VS_STRIDE + c] = vbase[(size_t)(kt + key) * HDIM + c];
        }
        __syncthreads();

        for (int kk = 0; kk < KT; kk++) {
            float p = sc[qi * SEQ + kt + kk];
            const float* vrow = &ksvs[kk * VS_STRIDE];
#pragma unroll
            for (int j = 0; j < 8; j++)
                cacc[j] = fmaf(p, vrow[dg + 8 * j], cacc[j]);
        }
    }

    // write ctx in [B,S,D] layout: d = h*64 + dg + 8j
    {
        int srow = qb * QB + qi;
        float* crow = ctx_out + ((size_t)b * SEQ + srow) * DMODEL + h * HDIM;
#pragma unroll
        for (int j = 0; j < 8; j++)
            crow[dg + 8 * j] = cacc[j];
    }
}

// -------------------- launcher ----------------------------------------------
extern "C" void kernel_launch(void* const* d_in, const int* in_sizes, int n_in,
                              void* d_out, int out_size)
{
    const float* x  = (const float*)d_in[0];
    const float* Wq = (const float*)d_in[1];
    const float* bq = (const float*)d_in[2];
    const float* Wk = (const float*)d_in[3];
    const float* bk = (const float*)d_in[4];
    const float* Wv = (const float*)d_in[5];
    const float* bv = (const float*)d_in[6];
    const float* Wo = (const float*)d_in[7];
    const float* bo = (const float*)d_in[8];

    float* out_ptr  = (float*)d_out;                                   // [B,S,D]
    float* attn_ptr = (float*)d_out + (size_t)BATCH * SEQ * DMODEL;    // [B,H,S,S]

    float *qp, *kp, *vp, *cp;
    cudaGetSymbolAddress((void**)&qp, g_q);
    cudaGetSymbolAddress((void**)&kp, g_k);
    cudaGetSymbolAddress((void**)&vp, g_v);
    cudaGetSymbolAddress((void**)&cp, g_ctx);

    cudaFuncSetAttribute(attn_kernel, cudaFuncAttributeMaxDynamicSharedMemorySize,
                         ATTN_SMEM_BYTES);

    dim3 gblk(256);
    dim3 ggrid(DMODEL / GBN, MTOT / GBM);    // (8, 64)

    gemm_bias_kernel<<<ggrid, gblk>>>(x, Wq, bq, qp, MTOT, DMODEL, DMODEL, 1);
    gemm_bias_kernel<<<ggrid, gblk>>>(x, Wk, bk, kp, MTOT, DMODEL, DMODEL, 1);
    gemm_bias_kernel<<<ggrid, gblk>>>(x, Wv, bv, vp, MTOT, DMODEL, DMODEL, 1);

    dim3 agrid(BATCH * HEADS, SEQ / QB);     // (128, 32)
    attn_kernel<<<agrid, gblk, ATTN_SMEM_BYTES>>>(qp, kp, vp, attn_ptr, cp);

    gemm_bias_kernel<<<ggrid, gblk>>>(cp, Wo, bo, out_ptr, MTOT, DMODEL, DMODEL, 0);
}

// round 3
// speedup vs baseline: 5.5854x; 5.5854x over previous
#include <cuda_runtime.h>
#include <math.h>

// Problem constants
#define BATCH  8
#define SEQ    1024
#define DMODEL 1024
#define HEADS  16
#define HDIM   64
#define MTOT   (BATCH * SEQ)          // 8192

// -------------------- scratch (__device__ globals; no allocs allowed) -------
__device__ float g_q[(size_t)BATCH * HEADS * SEQ * HDIM];   // [B,H,S,Hd]
__device__ float g_k[(size_t)BATCH * HEADS * SEQ * HDIM];
__device__ float g_v[(size_t)BATCH * HEADS * SEQ * HDIM];
__device__ float g_ctx[(size_t)BATCH * SEQ * DMODEL];       // [B,S,D]

// -------------------- TF32 mma.sync helpers ---------------------------------
__device__ __forceinline__ unsigned f2tf(float f) {
    unsigned u;
    asm("cvt.rna.tf32.f32 %0, %1;" : "=r"(u) : "f"(f));
    return u;
}

// D = A(16x8, row) * B(8x8, col) + D, tf32 inputs, fp32 accum
__device__ __forceinline__ void mma8(float* c, const unsigned* a, const unsigned* b) {
    asm volatile(
        "mma.sync.aligned.m16n8k8.row.col.f32.tf32.tf32.f32 "
        "{%0,%1,%2,%3}, {%4,%5,%6,%7}, {%8,%9}, {%0,%1,%2,%3};\n"
        : "+f"(c[0]), "+f"(c[1]), "+f"(c[2]), "+f"(c[3])
        : "r"(a[0]), "r"(a[1]), "r"(a[2]), "r"(a[3]), "r"(b[0]), "r"(b[1]));
}

// =============================================================================
// Projection GEMM: C[M,1024] = A[M,1024] * W[1024,1024]^T + bias
// BM=128, BN=128, BK=32; 8 warps, warp tile 64x32 (2x4 warp grid).
// =============================================================================
#define PSTR 36   // smem row stride (floats); 36 % 32 == 4 -> conflict-free frags

__global__ __launch_bounds__(256)
void proj_tf32_kernel(const float* __restrict__ A, const float* __restrict__ W,
                      const float* __restrict__ bias, float* __restrict__ C,
                      int split_heads)
{
    __shared__ unsigned As[128 * PSTR];
    __shared__ unsigned Bs[128 * PSTR];

    const int tid  = threadIdx.x;
    const int wid  = tid >> 5;
    const int lane = tid & 31;
    const int gid  = lane >> 2;   // 0..7
    const int tig  = lane & 3;    // 0..3
    const int m0 = blockIdx.y * 128;
    const int n0 = blockIdx.x * 128;
    const int wm = (wid >> 2) * 64;   // 0 or 64
    const int wn = (wid & 3) * 32;    // 0..96

    float acc[4][4][4];
#pragma unroll
    for (int mt = 0; mt < 4; mt++)
#pragma unroll
        for (int nt = 0; nt < 4; nt++)
#pragma unroll
            for (int r = 0; r < 4; r++) acc[mt][nt][r] = 0.0f;

    for (int kt = 0; kt < DMODEL; kt += 32) {
#pragma unroll
        for (int r = 0; r < 4; r++) {
            int idx = tid + r * 256;        // 0..1023
            int row = idx >> 3;             // 0..127
            int c4  = (idx & 7) * 4;        // 0..28
            float4 a4 = *(const float4*)(A + (size_t)(m0 + row) * DMODEL + kt + c4);
            unsigned* d = &As[row * PSTR + c4];
            d[0] = f2tf(a4.x); d[1] = f2tf(a4.y); d[2] = f2tf(a4.z); d[3] = f2tf(a4.w);
            float4 w4 = *(const float4*)(W + (size_t)(n0 + row) * DMODEL + kt + c4);
            unsigned* e = &Bs[row * PSTR + c4];
            e[0] = f2tf(w4.x); e[1] = f2tf(w4.y); e[2] = f2tf(w4.z); e[3] = f2tf(w4.w);
        }
        __syncthreads();

#pragma unroll
        for (int ks = 0; ks < 4; ks++) {
            unsigned af[4][4], bf[4][2];
#pragma unroll
            for (int mt = 0; mt < 4; mt++) {
                const unsigned* p  = &As[(wm + mt * 16 + gid) * PSTR + ks * 8 + tig];
                const unsigned* p2 = p + 8 * PSTR;
                af[mt][0] = p[0];  af[mt][2] = p[4];
                af[mt][1] = p2[0]; af[mt][3] = p2[4];
            }
#pragma unroll
            for (int nt = 0; nt < 4; nt++) {
                const unsigned* p = &Bs[(wn + nt * 8 + gid) * PSTR + ks * 8 + tig];
                bf[nt][0] = p[0]; bf[nt][1] = p[4];
            }
#pragma unroll
            for (int mt = 0; mt < 4; mt++)
#pragma unroll
                for (int nt = 0; nt < 4; nt++)
                    mma8(acc[mt][nt], af[mt], bf[nt]);
        }
        __syncthreads();
    }

    // epilogue: c0/c1 -> row gid, cols 2*tig,2*tig+1 ; c2/c3 -> row gid+8
#pragma unroll
    for (int mt = 0; mt < 4; mt++) {
#pragma unroll
        for (int half = 0; half < 2; half++) {
            int m  = m0 + wm + mt * 16 + gid + half * 8;
            int bb = m >> 10;
            int s  = m & 1023;
#pragma unroll
            for (int nt = 0; nt < 4; nt++) {
                int n = n0 + wn + nt * 8 + tig * 2;
                float2 v;
                v.x = acc[mt][nt][half * 2 + 0] + bias[n];
                v.y = acc[mt][nt][half * 2 + 1] + bias[n + 1];
                size_t idx;
                if (split_heads) {
                    int h = n >> 6, d = n & 63;
                    idx = ((((size_t)bb * HEADS + h) * SEQ + s) << 6) + d;
                } else {
                    idx = (size_t)m * DMODEL + n;
                }
                *(float2*)(C + idx) = v;
            }
        }
    }
}

// =============================================================================
// Scores GEMM: raw scaled scores -> attn buffer (pre-softmax)
// S[q,k] = (Q[q,:] . K[k,:]) * 0.125 for one (b,h); tiles 128x128, K=64.
// =============================================================================
#define SSTR 68   // 68 % 32 == 4 -> conflict-free

__global__ __launch_bounds__(256)
void scores_tf32_kernel(const float* __restrict__ q, const float* __restrict__ k,
                        float* __restrict__ attn)
{
    extern __shared__ unsigned sm[];
    unsigned* Qs = sm;                 // [128][SSTR]
    unsigned* Ks = sm + 128 * SSTR;    // [128][SSTR]

    const int tid  = threadIdx.x;
    const int wid  = tid >> 5;
    const int lane = tid & 31;
    const int gid  = lane >> 2;
    const int tig  = lane & 3;
    const int bh = blockIdx.z;
    const int q0 = blockIdx.y * 128;
    const int k0 = blockIdx.x * 128;
    const int wm = (wid >> 2) * 64;
    const int wn = (wid & 3) * 32;

    const float* qb = q + (size_t)bh * SEQ * HDIM;
    const float* kb = k + (size_t)bh * SEQ * HDIM;

#pragma unroll
    for (int r = 0; r < 8; r++) {
        int idx = tid + r * 256;        // 0..2047
        int row = idx >> 4;             // 0..127
        int c4  = (idx & 15) * 4;       // 0..60
        float4 a4 = *(const float4*)(qb + (size_t)(q0 + row) * HDIM + c4);
        unsigned* d = &Qs[row * SSTR + c4];
        d[0] = f2tf(a4.x); d[1] = f2tf(a4.y); d[2] = f2tf(a4.z); d[3] = f2tf(a4.w);
        float4 b4 = *(const float4*)(kb + (size_t)(k0 + row) * HDIM + c4);
        unsigned* e = &Ks[row * SSTR + c4];
        e[0] = f2tf(b4.x); e[1] = f2tf(b4.y); e[2] = f2tf(b4.z); e[3] = f2tf(b4.w);
    }
    __syncthreads();

    float acc[4][4][4];
#pragma unroll
    for (int mt = 0; mt < 4; mt++)
#pragma unroll
        for (int nt = 0; nt < 4; nt++)
#pragma unroll
            for (int r = 0; r < 4; r++) acc[mt][nt][r] = 0.0f;

#pragma unroll
    for (int ks = 0; ks < 8; ks++) {
        unsigned af[4][4], bf[4][2];
#pragma unroll
        for (int mt = 0; mt < 4; mt++) {
            const unsigned* p  = &Qs[(wm + mt * 16 + gid) * SSTR + ks * 8 + tig];
            const unsigned* p2 = p + 8 * SSTR;
            af[mt][0] = p[0];  af[mt][2] = p[4];
            af[mt][1] = p2[0]; af[mt][3] = p2[4];
        }
#pragma unroll
        for (int nt = 0; nt < 4; nt++) {
            const unsigned* p = &Ks[(wn + nt * 8 + gid) * SSTR + ks * 8 + tig];
            bf[nt][0] = p[0]; bf[nt][1] = p[4];
        }
#pragma unroll
        for (int mt = 0; mt < 4; mt++)
#pragma unroll
            for (int nt = 0; nt < 4; nt++)
                mma8(acc[mt][nt], af[mt], bf[nt]);
    }

    float* ab = attn + (size_t)bh * SEQ * SEQ;
#pragma unroll
    for (int mt = 0; mt < 4; mt++) {
#pragma unroll
        for (int half = 0; half < 2; half++) {
            int sq = q0 + wm + mt * 16 + gid + half * 8;
#pragma unroll
            for (int nt = 0; nt < 4; nt++) {
                int sk = k0 + wn + nt * 8 + tig * 2;
                float2 v;
                v.x = acc[mt][nt][half * 2 + 0] * 0.125f;
                v.y = acc[mt][nt][half * 2 + 1] * 0.125f;
                *(float2*)(ab + (size_t)sq * SEQ + sk) = v;
            }
        }
    }
}

// =============================================================================
// Row softmax over attn (in place). One warp per row of 1024 floats.
// =============================================================================
__global__ __launch_bounds__(256)
void softmax_kernel(float* __restrict__ attn)
{
    const int wid  = threadIdx.x >> 5;
    const int lane = threadIdx.x & 31;
    size_t row = (size_t)blockIdx.x * 8 + wid;
    float4* p = (float4*)(attn + row * SEQ);

    float4 v[8];
    float mx = -1e30f;
#pragma unroll
    for (int r = 0; r < 8; r++) {
        v[r] = p[r * 32 + lane];
        mx = fmaxf(mx, fmaxf(fmaxf(v[r].x, v[r].y), fmaxf(v[r].z, v[r].w)));
    }
#pragma unroll
    for (int off = 16; off > 0; off >>= 1)
        mx = fmaxf(mx, __shfl_xor_sync(0xffffffffu, mx, off));

    float sum = 0.0f;
#pragma unroll
    for (int r = 0; r < 8; r++) {
        v[r].x = __expf(v[r].x - mx);
        v[r].y = __expf(v[r].y - mx);
        v[r].z = __expf(v[r].z - mx);
        v[r].w = __expf(v[r].w - mx);
        sum += v[r].x + v[r].y + v[r].z + v[r].w;
    }
#pragma unroll
    for (int off = 16; off > 0; off >>= 1)
        sum += __shfl_xor_sync(0xffffffffu, sum, off);
    float inv = 1.0f / sum;

#pragma unroll
    for (int r = 0; r < 8; r++) {
        v[r].x *= inv; v[r].y *= inv; v[r].z *= inv; v[r].w *= inv;
        p[r * 32 + lane] = v[r];
    }
}

// =============================================================================
// Context GEMM: ctx[q,d] = sum_k P[q,k] * V[k,d] per (b,h).
// BM=256, N=64, BK=32; 8 warps, warp tile 32x64.
// =============================================================================
#define CSTR 36
#define VSTR 72   // 72 % 32 == 8 -> conflict-free for [k][n] B-frag loads

__global__ __launch_bounds__(256)
void ctx_tf32_kernel(const float* __restrict__ attn, const float* __restrict__ v,
                     float* __restrict__ ctx)
{
    __shared__ unsigned Ps[256 * CSTR];  // 36864 B
    __shared__ unsigned Vs[32 * VSTR];   //  9216 B

    const int tid  = threadIdx.x;
    const int wid  = tid >> 5;    // 0..7 -> 32 q-rows each
    const int lane = tid & 31;
    const int gid  = lane >> 2;
    const int tig  = lane & 3;
    const int bh = blockIdx.y;
    const int q0 = blockIdx.x * 256;
    const int b = bh >> 4, h = bh & 15;

    const float* pb = attn + (size_t)bh * SEQ * SEQ;
    const float* vb = v + (size_t)bh * SEQ * HDIM;

    float acc[2][8][4];
#pragma unroll
    for (int mt = 0; mt < 2; mt++)
#pragma unroll
        for (int nt = 0; nt < 8; nt++)
#pragma unroll
            for (int r = 0; r < 4; r++) acc[mt][nt][r] = 0.0f;

    for (int kt = 0; kt < SEQ; kt += 32) {
#pragma unroll
        for (int r = 0; r < 8; r++) {
            int idx = tid + r * 256;     // 0..2047
            int row = idx >> 3;          // 0..255
            int c4  = (idx & 7) * 4;     // 0..28
            float4 a4 = *(const float4*)(pb + (size_t)(q0 + row) * SEQ + kt + c4);
            unsigned* d = &Ps[row * CSTR + c4];
            d[0] = f2tf(a4.x); d[1] = f2tf(a4.y); d[2] = f2tf(a4.z); d[3] = f2tf(a4.w);
        }
#pragma unroll
        for (int r = 0; r < 2; r++) {
            int idx = tid + r * 256;     // 0..511
            int row = idx >> 4;          // 0..31
            int c4  = (idx & 15) * 4;    // 0..60
            float4 b4 = *(const float4*)(vb + (size_t)(kt + row) * HDIM + c4);
            unsigned* e = &Vs[row * VSTR + c4];
            e[0] = f2tf(b4.x); e[1] = f2tf(b4.y); e[2] = f2tf(b4.z); e[3] = f2tf(b4.w);
        }
        __syncthreads();

#pragma unroll
        for (int ks = 0; ks < 4; ks++) {
            unsigned af[2][4], bf[8][2];
#pragma unroll
            for (int mt = 0; mt < 2; mt++) {
                const unsigned* p  = &Ps[(wid * 32 + mt * 16 + gid) * CSTR + ks * 8 + tig];
                const unsigned* p2 = p + 8 * CSTR;
                af[mt][0] = p[0];  af[mt][2] = p[4];
                af[mt][1] = p2[0]; af[mt][3] = p2[4];
            }
#pragma unroll
            for (int nt = 0; nt < 8; nt++) {
                const unsigned* p = &Vs[(ks * 8 + tig) * VSTR + nt * 8 + gid];
                bf[nt][0] = p[0]; bf[nt][1] = p[4 * VSTR];
            }
#pragma unroll
            for (int mt = 0; mt < 2; mt++)
#pragma unroll
                for (int nt = 0; nt < 8; nt++)
                    mma8(acc[mt][nt], af[mt], bf[nt]);
        }
        __syncthreads();
    }

#pragma unroll
    for (int mt = 0; mt < 2; mt++) {
#pragma unroll
        for (int half = 0; half < 2; half++) {
            int qrow = q0 + wid * 32 + mt * 16 + gid + half * 8;
            float* crow = ctx + ((size_t)b * SEQ + qrow) * DMODEL + h * HDIM;
#pragma unroll
            for (int nt = 0; nt < 8; nt++) {
                int d = nt * 8 + tig * 2;
                float2 o;
                o.x = acc[mt][nt][half * 2 + 0];
                o.y = acc[mt][nt][half * 2 + 1];
                *(float2*)(crow + d) = o;
            }
        }
    }
}

// -------------------- launcher ----------------------------------------------
extern "C" void kernel_launch(void* const* d_in, const int* in_sizes, int n_in,
                              void* d_out, int out_size)
{
    const float* x  = (const float*)d_in[0];
    const float* Wq = (const float*)d_in[1];
    const float* bq = (const float*)d_in[2];
    const float* Wk = (const float*)d_in[3];
    const float* bk = (const float*)d_in[4];
    const float* Wv = (const float*)d_in[5];
    const float* bv = (const float*)d_in[6];
    const float* Wo = (const float*)d_in[7];
    const float* bo = (const float*)d_in[8];

    float* out_ptr  = (float*)d_out;                                   // [B,S,D]
    float* attn_ptr = (float*)d_out + (size_t)BATCH * SEQ * DMODEL;    // [B,H,S,S]

    float *qp, *kp, *vp, *cp;
    cudaGetSymbolAddress((void**)&qp, g_q);
    cudaGetSymbolAddress((void**)&kp, g_k);
    cudaGetSymbolAddress((void**)&vp, g_v);
    cudaGetSymbolAddress((void**)&cp, g_ctx);

    cudaFuncSetAttribute(scores_tf32_kernel,
                         cudaFuncAttributeMaxDynamicSharedMemorySize,
                         2 * 128 * SSTR * 4);

    dim3 blk(256);
    dim3 pgrid(DMODEL / 128, MTOT / 128);       // (8, 64)

    proj_tf32_kernel<<<pgrid, blk>>>(x, Wq, bq, qp, 1);
    proj_tf32_kernel<<<pgrid, blk>>>(x, Wk, bk, kp, 1);
    proj_tf32_kernel<<<pgrid, blk>>>(x, Wv, bv, vp, 1);

    dim3 sgrid(SEQ / 128, SEQ / 128, BATCH * HEADS);   // (8, 8, 128)
    scores_tf32_kernel<<<sgrid, blk, 2 * 128 * SSTR * 4>>>(qp, kp, attn_ptr);

    softmax_kernel<<<(BATCH * HEADS * SEQ) / 8, blk>>>(attn_ptr);

    dim3 cgrid(SEQ / 256, BATCH * HEADS);              // (4, 128)
    ctx_tf32_kernel<<<cgrid, blk>>>(attn_ptr, vp, cp);

    proj_tf32_kernel<<<pgrid, blk>>>(cp, Wo, bo, out_ptr, 0);
}